// round 16
// baseline (speedup 1.0000x reference)
#include <cuda_runtime.h>
#include <cstdint>
#include <math.h>

#define BB 512
#define DD 2048
#define KK 128
#define PP 5
#define NN (KK * PP)      // 640
#define OUTW (DD + KK)    // 2176

#define SPLIT 4
#define KC (DD / SPLIT)   // 512 K per CTA
#define TM 64
#define TN 80
#define ROWP 36           // A row pad (floats): conflict-free LDS.32 + 16B-aligned
#define BROWP 88          // B row pad (floats): 88%32==24 -> conflict-free, 352B/row
#define B_OFF (TM * ROWP)                   // 2304 floats
#define STG_FLOATS (B_OFF + 32 * BROWP)     // 2304 + 2816 = 5120 floats = 20480B
#define NSTAGE 4
#define GEMM_SMEM (NSTAGE * STG_FLOATS * 4) // 81920 B -> 2 CTAs/SM

// ---------------- scratch (no cudaMalloc allowed) ----------------
__device__ float g_part[SPLIT * BB * NN];  // K-split partial actv (unscaled)
__device__ float g_nrm[8 * NN];            // per-d-chunk partial sum-of-squares
__device__ float g_xr[BB * DD];            // x rounded to tf32 (rna)
__device__ float g_btr[DD * NN];           // theta rounded to tf32, [d][n] layout

__device__ __forceinline__ float rna_tf32(float v) {
    uint32_t u;
    asm("cvt.rna.tf32.f32 %0, %1;" : "=r"(u) : "f"(v));
    return __uint_as_float(u);
}
__device__ __forceinline__ uint32_t s2u(const void* p) {
    uint32_t a;
    asm("{ .reg .u64 t; cvta.to.shared.u64 t, %1; cvt.u32.u64 %0, t; }"
        : "=r"(a) : "l"(p));
    return a;
}
#define EX2(d, a) asm("ex2.approx.ftz.f32 %0, %1;" : "=f"(d) : "f"(a))

// ---------------------------------------------------------------------------
// 1) fused prep kernel (frozen R15), 3 roles by blockIdx.x, 256 threads each
// ---------------------------------------------------------------------------
#define PREP_NORM_B 160
#define PREP_RB_B 320
#define PREP_RX_B 256
#define PREP_BLOCKS (PREP_NORM_B + PREP_RB_B + PREP_RX_B)

__global__ __launch_bounds__(256) void prep_kernel(const float* __restrict__ x,
                                                   const float* __restrict__ theta,
                                                   float* __restrict__ out) {
    __shared__ float smem[8][32];
    const int bid = blockIdx.x;
    const int tid = threadIdx.x;

    if (bid < PREP_NORM_B) {
        int cg = bid % 20;
        int chunk = bid / 20;
        int c = tid & 31;
        int q = tid >> 5;
        int col = cg * 32 + c;
        int d0 = chunk * 256;
        float s = 0.f;
#pragma unroll 4
        for (int d = d0 + q; d < d0 + 256; d += 8) {
            float v = theta[(size_t)d * NN + col];
            s += v * v;
        }
        smem[q][c] = s;
        __syncthreads();
        if (q == 0) {
            float t = 0.f;
#pragma unroll
            for (int i = 0; i < 8; i++) t += smem[i][c];
            g_nrm[chunk * NN + col] = t;
        }
    } else if (bid < PREP_NORM_B + PREP_RB_B) {
        int bR = bid - PREP_NORM_B;
        const float4* ti = (const float4*)theta;
        float4* to = (float4*)g_btr;
        int n4 = DD * NN / 4;
        for (int i = bR * 256 + tid; i < n4; i += PREP_RB_B * 256) {
            float4 v = ti[i];
            v.x = rna_tf32(v.x); v.y = rna_tf32(v.y);
            v.z = rna_tf32(v.z); v.w = rna_tf32(v.w);
            to[i] = v;
        }
    } else {
        int bR = bid - PREP_NORM_B - PREP_RB_B;
        const float4* xi = (const float4*)x;
        float4* xo = (float4*)g_xr;
        int n4 = BB * DD / 4;
        for (int i = bR * 256 + tid; i < n4; i += PREP_RX_B * 256) {
            float4 v = xi[i];
            int row = i >> 9;
            int c4 = i & 511;
            *(float4*)&out[(size_t)row * OUTW + c4 * 4] = v;
            v.x = rna_tf32(v.x); v.y = rna_tf32(v.y);
            v.z = rna_tf32(v.z); v.w = rna_tf32(v.w);
            xo[i] = v;
        }
    }
}

// ---------------------------------------------------------------------------
// 2) tf32 mma.sync GEMM, cp.async 4-stage ring, 2 CTAs/SM.
//    CTA: 64m x 80n x KC=512. 128 thr, 4 warps (2m x 2n), warp tile 32x40.
//    grid (8, 8, 4) = 256 CTAs -> 2 co-resident CTAs with independent barriers.
// ---------------------------------------------------------------------------
__device__ __forceinline__ void mma_tf32(float* c,
                                         float a0, float a1, float a2, float a3,
                                         float b0, float b1) {
    asm volatile(
        "mma.sync.aligned.m16n8k8.row.col.f32.tf32.tf32.f32 "
        "{%0,%1,%2,%3}, {%4,%5,%6,%7}, {%8,%9}, {%0,%1,%2,%3};"
        : "+f"(c[0]), "+f"(c[1]), "+f"(c[2]), "+f"(c[3])
        : "r"(__float_as_uint(a0)), "r"(__float_as_uint(a1)),
          "r"(__float_as_uint(a2)), "r"(__float_as_uint(a3)),
          "r"(__float_as_uint(b0)), "r"(__float_as_uint(b1)));
}

__global__ __launch_bounds__(128, 2) void gemm_mma_kernel() {
    extern __shared__ float sm[];
    const int tid = threadIdx.x, lane = tid & 31, wid = tid >> 5;
    const int wm = wid & 1;        // m warp (32 rows)
    const int wn = wid >> 1;       // n warp (40 cols), 0..1
    const int mBase = blockIdx.y * TM;
    const int nBase = blockIdx.x * TN;
    const size_t kbase0 = (size_t)blockIdx.z * KC;

    // producer: q 0..3 -> A chunks (512), q 4..8 -> B chunks (640)
    size_t srcg[9];
    uint32_t dsts[9];
    const uint32_t sb = s2u(sm);
#pragma unroll
    for (int q = 0; q < 9; q++) {
        int c = tid + q * 128;
        const float* src;
        uint32_t d;
        if (c < 512) {                          // A: 64 rows x 8 chunks of 16B
            int r = c >> 3, p = c & 7;
            src = g_xr + (size_t)(mBase + r) * DD + kbase0 + p * 4;
            d = (uint32_t)(r * ROWP + p * 4) * 4;
        } else {                                // B: 32 k-rows x 20 chunks of 16B
            int cb = c - 512;
            int k = cb / 20, p = cb % 20;
            src = g_btr + (kbase0 + k) * NN + nBase + p * 4;
            d = (uint32_t)(B_OFF + k * BROWP + p * 4) * 4;
        }
        srcg[q] = __cvta_generic_to_global(src);
        dsts[q] = sb + d;
    }

#define LOAD_STAGE(it_) do {                                               \
    uint32_t soff_ = (uint32_t)(((it_) & 3) * (STG_FLOATS * 4));           \
    size_t goA_ = (size_t)(it_) * 128;                                     \
    size_t goB_ = (size_t)(it_) * (32 * NN * 4);                           \
    _Pragma("unroll")                                                      \
    for (int q_ = 0; q_ < 4; q_++)                                         \
        asm volatile("cp.async.cg.shared.global [%0], [%1], 16;"           \
                     :: "r"(dsts[q_] + soff_), "l"(srcg[q_] + goA_));      \
    _Pragma("unroll")                                                      \
    for (int q_ = 4; q_ < 9; q_++)                                         \
        asm volatile("cp.async.cg.shared.global [%0], [%1], 16;"           \
                     :: "r"(dsts[q_] + soff_), "l"(srcg[q_] + goB_));      \
    asm volatile("cp.async.commit_group;" ::: "memory");                   \
} while (0)

    LOAD_STAGE(0);
    LOAD_STAGE(1);
    LOAD_STAGE(2);

    float acc[5][2][4] = {};
    const int aRow = wm * 32 + (lane >> 2);
    const int kCol = lane & 3;
    const int bN = wn * 40 + (lane >> 2);

    const int NIT = KC / 32;   // 16
#pragma unroll 1
    for (int it = 0; it < NIT; ++it) {
        asm volatile("cp.async.wait_group 2;" ::: "memory");
        __syncthreads();
        const float* s = sm + (it & 3) * STG_FLOATS;

#pragma unroll
        for (int ks = 0; ks < 4; ++ks) {
            float a[2][4];
#pragma unroll
            for (int ms = 0; ms < 2; ++ms) {
                const float* ap = s + (aRow + ms * 16) * ROWP + ks * 8 + kCol;
                a[ms][0] = ap[0];
                a[ms][1] = ap[8 * ROWP];
                a[ms][2] = ap[4];
                a[ms][3] = ap[8 * ROWP + 4];
            }
            const float* bp = s + B_OFF + (ks * 8 + kCol) * BROWP + bN;
#pragma unroll
            for (int nb = 0; nb < 5; ++nb) {
                float b0 = bp[nb * 8];
                float b1 = bp[4 * BROWP + nb * 8];
                mma_tf32(acc[nb][0], a[0][0], a[0][1], a[0][2], a[0][3], b0, b1);
                mma_tf32(acc[nb][1], a[1][0], a[1][1], a[1][2], a[1][3], b0, b1);
            }
        }
        __syncthreads();
        if (it + 3 < NIT) LOAD_STAGE(it + 3);
        else asm volatile("cp.async.commit_group;" ::: "memory");
    }

    float* op = g_part + (size_t)blockIdx.z * BB * NN;
    const int row0 = mBase + wm * 32 + (lane >> 2);
    const int col0 = nBase + wn * 40 + (lane & 3) * 2;
#pragma unroll
    for (int nb = 0; nb < 5; ++nb) {
#pragma unroll
        for (int ms = 0; ms < 2; ++ms) {
            int row = row0 + ms * 16;
            int col = col0 + nb * 8;
            *(float2*)&op[(size_t)row * NN + col] =
                make_float2(acc[nb][ms][0], acc[nb][ms][1]);
            *(float2*)&op[(size_t)(row + 8) * NN + col] =
                make_float2(acc[nb][ms][2], acc[nb][ms][3]);
        }
    }
#undef LOAD_STAGE
}

// ---------------------------------------------------------------------------
// 3) pairwise, scalar min-trick with i-pairing (frozen R15)
// ---------------------------------------------------------------------------
__global__ __launch_bounds__(256, 1)
void pairwise_kernel(const float* __restrict__ lws,
                     const float* __restrict__ bias, float* __restrict__ out) {
    const int k = blockIdx.x;
    const int t = threadIdx.x;
    __shared__ float sD[BB][8];    // 2a0..2a4, Sj
    __shared__ float sSc[5];

    if (t < 5) {
        int col = k * PP + t;
        float n2 = 0.f;
#pragma unroll
        for (int c = 0; c < 8; c++) n2 += g_nrm[c * NN + col];
        sSc[t] = __expf(lws[col]) * rsqrtf(n2) * 1.4426950408889634f;
    }

    float s_[2][5];
#pragma unroll
    for (int r = 0; r < 2; r++) {
        int i = t + r * 256;
        float s0 = 0.f, s1 = 0.f, s2 = 0.f, s3 = 0.f, s4 = 0.f;
#pragma unroll
        for (int s = 0; s < SPLIT; s++) {
            const float* p = g_part + (size_t)s * BB * NN + (size_t)i * NN + k * PP;
            s0 += p[0]; s1 += p[1]; s2 += p[2]; s3 += p[3]; s4 += p[4];
        }
        s_[r][0] = s0; s_[r][1] = s1; s_[r][2] = s2; s_[r][3] = s3; s_[r][4] = s4;
    }
    __syncthreads();

    float d[2][5], Si[2];
#pragma unroll
    for (int r = 0; r < 2; r++) {
        int i = t + r * 256;
        float a0 = s_[r][0] * sSc[0], a1 = s_[r][1] * sSc[1];
        float a2 = s_[r][2] * sSc[2], a3 = s_[r][3] * sSc[3];
        float a4 = s_[r][4] * sSc[4];
        Si[r] = ((a0 + a1) + (a2 + a3)) + a4;
        d[r][0] = a0 + a0; d[r][1] = a1 + a1; d[r][2] = a2 + a2;
        d[r][3] = a3 + a3; d[r][4] = a4 + a4;
        sD[i][0] = d[r][0]; sD[i][1] = d[r][1]; sD[i][2] = d[r][2];
        sD[i][3] = d[r][3]; sD[i][4] = d[r][4]; sD[i][5] = Si[r];
    }
    __syncthreads();

    float acc0 = 0.f, acc1 = 0.f;
#pragma unroll 8
    for (int j = 0; j < BB; j++) {
        float4 v = *(const float4*)&sD[j][0];
        float2 w = *(const float2*)&sD[j][4];
        float m0 = fminf(d[0][0], v.x);
        float m1 = fminf(d[0][1], v.y);
        float m2 = fminf(d[0][2], v.z);
        float m3 = fminf(d[0][3], v.w);
        float m4 = fminf(d[0][4], w.x);
        float arg0 = ((m0 + m1) + (m2 + m3)) + (m4 - w.y);
        float e0;
        EX2(e0, arg0);
        acc0 += e0;
        float n0 = fminf(d[1][0], v.x);
        float n1 = fminf(d[1][1], v.y);
        float n2 = fminf(d[1][2], v.z);
        float n3 = fminf(d[1][3], v.w);
        float n4 = fminf(d[1][4], w.x);
        float arg1 = ((n0 + n1) + (n2 + n3)) + (n4 - w.y);
        float e1;
        EX2(e1, arg1);
        acc1 += e1;
    }
    float sc0, sc1;
    EX2(sc0, -Si[0]);
    EX2(sc1, -Si[1]);
    float bk = bias[k] - 1.0f;
    out[(size_t)t * OUTW + DD + k] = fmaf(acc0, sc0, bk);
    out[(size_t)(t + 256) * OUTW + DD + k] = fmaf(acc1, sc1, bk);
}

// ---------------------------------------------------------------------------
extern "C" void kernel_launch(void* const* d_in, const int* in_sizes, int n_in,
                              void* d_out, int out_size) {
    const float* x     = (const float*)d_in[0];   // [512, 2048]
    const float* theta = (const float*)d_in[1];   // [2048, 128, 5]
    const float* lws   = (const float*)d_in[2];   // [128, 5]
    const float* bias  = (const float*)d_in[3];   // [128]
    float* out = (float*)d_out;                   // [512, 2176]

    cudaFuncSetAttribute(gemm_mma_kernel,
                         cudaFuncAttributeMaxDynamicSharedMemorySize, GEMM_SMEM);

    prep_kernel<<<PREP_BLOCKS, 256>>>(x, theta, out);
    gemm_mma_kernel<<<dim3(NN / TN, BB / TM, SPLIT), 128, GEMM_SMEM>>>();
    pairwise_kernel<<<KK, BB / 2>>>(lws, bias, out);
}

// round 17
// speedup vs baseline: 1.1065x; 1.1065x over previous
#include <cuda_runtime.h>
#include <cuda_fp16.h>
#include <cstdint>
#include <math.h>

#define BB 512
#define DD 2048
#define KK 128
#define PP 5
#define NN (KK * PP)      // 640
#define OUTW (DD + KK)    // 2176

#define SPLIT 4
#define KC (DD / SPLIT)   // 512 K per CTA
#define TM 64
#define TN 160
#define PITCHH 40         // row pitch in halves (80B): conflict-free + 16B-aligned
#define B_OFF_B (TM * PITCHH * 2)             // 5120 bytes
#define STG_BYTES ((TM + TN) * PITCHH * 2)    // 17920 bytes
#define NSTAGE 4
#define GEMM_SMEM (NSTAGE * STG_BYTES)        // 71680 B

// ---------------- scratch (no cudaMalloc allowed) ----------------
__device__ float g_part[SPLIT * BB * NN];  // K-split partial actv (unscaled)
__device__ float g_nrm[8 * NN];            // per-d-chunk partial sum-of-squares
__device__ __half g_xh[BB * DD];           // x as fp16 (rn)
__device__ __half g_bth[NN * DD];          // theta^T as fp16 (rn), [n][d] K-major

__device__ __forceinline__ uint32_t s2u(const void* p) {
    uint32_t a;
    asm("{ .reg .u64 t; cvta.to.shared.u64 t, %1; cvt.u32.u64 %0, t; }"
        : "=r"(a) : "l"(p));
    return a;
}
#define EX2(d, a) asm("ex2.approx.ftz.f32 %0, %1;" : "=f"(d) : "f"(a))

// ---------------------------------------------------------------------------
// 1) fused prep kernel, 3 roles by blockIdx.x, 256 threads each:
//    [0,160):      norm partials: g_nrm[chunk][col] = sum_{256 d in chunk} theta^2
//    [160,1440):   transpose: g_bth[n][d] = half(theta[d][n])
//    [1440,1696):  g_xh = half(x); out[:, :2048] = x  (raw copy)
// ---------------------------------------------------------------------------
#define PREP_NORM_B 160
#define PREP_TR_B 1280
#define PREP_RX_B 256
#define PREP_BLOCKS (PREP_NORM_B + PREP_TR_B + PREP_RX_B)

__global__ __launch_bounds__(256) void prep_kernel(const float* __restrict__ x,
                                                   const float* __restrict__ theta,
                                                   float* __restrict__ out) {
    __shared__ float smem[32][33];
    const int bid = blockIdx.x;
    const int tid = threadIdx.x;

    if (bid < PREP_NORM_B) {
        // ---- norm-partial role ----
        int cg = bid % 20;
        int chunk = bid / 20;
        int c = tid & 31;
        int q = tid >> 5;
        int col = cg * 32 + c;
        int d0 = chunk * 256;
        float s = 0.f;
#pragma unroll 4
        for (int d = d0 + q; d < d0 + 256; d += 8) {
            float v = theta[(size_t)d * NN + col];
            s += v * v;
        }
        smem[q][c] = s;
        __syncthreads();
        if (q == 0) {
            float t = 0.f;
#pragma unroll
            for (int i = 0; i < 8; i++) t += smem[i][c];
            g_nrm[chunk * NN + col] = t;
        }
    } else if (bid < PREP_NORM_B + PREP_TR_B) {
        // ---- transpose role: 32x32 tile, write fp16 K-major ----
        int bt = bid - PREP_NORM_B;
        int n0 = (bt % 20) * 32;
        int d0 = (bt / 20) * 32;
        int tx = tid & 31, ty = tid >> 5;
#pragma unroll
        for (int i = 0; i < 4; i++) {
            int r = ty + i * 8;
            smem[r][tx] = theta[(size_t)(d0 + r) * NN + n0 + tx];
        }
        __syncthreads();
#pragma unroll
        for (int i = 0; i < 4; i++) {
            int r = ty + i * 8;
            g_bth[(size_t)(n0 + r) * DD + d0 + tx] = __float2half_rn(smem[tx][r]);
        }
    } else {
        // ---- round_x + copy role ----
        int bR = bid - PREP_NORM_B - PREP_TR_B;
        const float4* xi = (const float4*)x;
        int n4 = BB * DD / 4;
        for (int i = bR * 256 + tid; i < n4; i += PREP_RX_B * 256) {
            float4 v = xi[i];
            int row = i >> 9;
            int c4 = i & 511;
            *(float4*)&out[(size_t)row * OUTW + c4 * 4] = v;   // raw copy
            __half2* hp = (__half2*)(g_xh + (size_t)row * DD + c4 * 4);
            hp[0] = __floats2half2_rn(v.x, v.y);
            hp[1] = __floats2half2_rn(v.z, v.w);
        }
    }
}

// ---------------------------------------------------------------------------
// 2) fp16 mma.sync m16n8k16 GEMM, cp.async 4-stage ring.
//    CTA: 64m x 160n x KC=512, 256 thr, 8 warps (2m x 4n), warp tile 32x40.
//    Both tiles K-major fp16, pitch 40 halves. grid (4, 8, 4) = 128 CTAs.
// ---------------------------------------------------------------------------
__device__ __forceinline__ void mma_f16(float* c, uint32_t a0, uint32_t a1,
                                        uint32_t a2, uint32_t a3,
                                        uint32_t b0, uint32_t b1) {
    asm volatile(
        "mma.sync.aligned.m16n8k16.row.col.f32.f16.f16.f32 "
        "{%0,%1,%2,%3}, {%4,%5,%6,%7}, {%8,%9}, {%0,%1,%2,%3};"
        : "+f"(c[0]), "+f"(c[1]), "+f"(c[2]), "+f"(c[3])
        : "r"(a0), "r"(a1), "r"(a2), "r"(a3), "r"(b0), "r"(b1));
}

__global__ __launch_bounds__(256, 1) void gemm_mma_kernel() {
    extern __shared__ char smc[];
    const int tid = threadIdx.x, lane = tid & 31, wid = tid >> 5;
    const int wm = wid & 1;        // m warp (32 rows)
    const int wn = wid >> 1;       // n warp (40 cols)
    const int mBase = blockIdx.y * TM;
    const int nBase = blockIdx.x * TN;
    const size_t kbase0 = (size_t)blockIdx.z * KC;

    // ---- producer: 896 16B-chunks/stage (A 256 + B 640), 3-4 per thread ----
    size_t srcg[4];
    uint32_t dsts[4];
    const uint32_t sb = s2u(smc);
    const int nq = (tid < 128) ? 4 : 3;     // 896 = 3*256 + 128
#pragma unroll
    for (int q = 0; q < 4; q++) {
        int c = tid + q * 256;
        if (c >= 896) break;
        const __half* src;
        uint32_t d;
        if (c < 256) {                       // A: 64 rows x 4 chunks of 16B
            int r = c >> 2, p = c & 3;
            src = g_xh + (size_t)(mBase + r) * DD + kbase0 + p * 8;
            d = (uint32_t)(r * PITCHH * 2 + p * 16);
        } else {                             // B: 160 rows x 4 chunks
            int cb = c - 256;
            int n = cb >> 2, p = cb & 3;
            src = g_bth + (size_t)(nBase + n) * DD + kbase0 + p * 8;
            d = (uint32_t)(B_OFF_B + n * PITCHH * 2 + p * 16);
        }
        srcg[q] = __cvta_generic_to_global(src);
        dsts[q] = sb + d;
    }

#define LOAD_STAGE(it_) do {                                               \
    uint32_t soff_ = (uint32_t)(((it_) & 3) * STG_BYTES);                  \
    size_t go_ = (size_t)(it_) * 64;       /* 32 halves per stage */       \
    _Pragma("unroll")                                                      \
    for (int q_ = 0; q_ < 4; q_++)                                         \
        if (q_ < nq)                                                       \
            asm volatile("cp.async.cg.shared.global [%0], [%1], 16;"       \
                         :: "r"(dsts[q_] + soff_), "l"(srcg[q_] + go_));   \
    asm volatile("cp.async.commit_group;" ::: "memory");                   \
} while (0)

    LOAD_STAGE(0);
    LOAD_STAGE(1);
    LOAD_STAGE(2);

    float acc[5][2][4] = {};
    // fragment byte offsets within tile
    const int aByte = (wm * 32 + (lane >> 2)) * (PITCHH * 2) + (lane & 3) * 4;
    const int bByte = B_OFF_B + (wn * 40 + (lane >> 2)) * (PITCHH * 2) + (lane & 3) * 4;

    const int NIT = KC / 32;   // 16 (two k16 mma steps per iter)
#pragma unroll 1
    for (int it = 0; it < NIT; ++it) {
        asm volatile("cp.async.wait_group 2;" ::: "memory");
        __syncthreads();
        const char* s = smc + (it & 3) * STG_BYTES;

#pragma unroll
        for (int ks = 0; ks < 2; ++ks) {     // k16 steps
            uint32_t a[2][4];
#pragma unroll
            for (int ms = 0; ms < 2; ++ms) {
                const char* ap = s + aByte + ms * 16 * (PITCHH * 2) + ks * 32;
                a[ms][0] = *(const uint32_t*)(ap);
                a[ms][1] = *(const uint32_t*)(ap + 8 * (PITCHH * 2));
                a[ms][2] = *(const uint32_t*)(ap + 16);
                a[ms][3] = *(const uint32_t*)(ap + 8 * (PITCHH * 2) + 16);
            }
#pragma unroll
            for (int nb = 0; nb < 5; ++nb) {
                const char* bp = s + bByte + nb * 8 * (PITCHH * 2) + ks * 32;
                uint32_t b0 = *(const uint32_t*)(bp);
                uint32_t b1 = *(const uint32_t*)(bp + 16);
                mma_f16(acc[nb][0], a[0][0], a[0][1], a[0][2], a[0][3], b0, b1);
                mma_f16(acc[nb][1], a[1][0], a[1][1], a[1][2], a[1][3], b0, b1);
            }
        }
        __syncthreads();
        if (it + 3 < NIT) LOAD_STAGE(it + 3);
        else asm volatile("cp.async.commit_group;" ::: "memory");
    }

    float* op = g_part + (size_t)blockIdx.z * BB * NN;
    const int row0 = mBase + wm * 32 + (lane >> 2);
    const int col0 = nBase + wn * 40 + (lane & 3) * 2;
#pragma unroll
    for (int nb = 0; nb < 5; ++nb) {
#pragma unroll
        for (int ms = 0; ms < 2; ++ms) {
            int row = row0 + ms * 16;
            int col = col0 + nb * 8;
            *(float2*)&op[(size_t)row * NN + col] =
                make_float2(acc[nb][ms][0], acc[nb][ms][1]);
            *(float2*)&op[(size_t)(row + 8) * NN + col] =
                make_float2(acc[nb][ms][2], acc[nb][ms][3]);
        }
    }
#undef LOAD_STAGE
}

// ---------------------------------------------------------------------------
// 3) pairwise, scalar min-trick with i-pairing (frozen R15)
// ---------------------------------------------------------------------------
__global__ __launch_bounds__(256, 1)
void pairwise_kernel(const float* __restrict__ lws,
                     const float* __restrict__ bias, float* __restrict__ out) {
    const int k = blockIdx.x;
    const int t = threadIdx.x;
    __shared__ float sD[BB][8];    // 2a0..2a4, Sj
    __shared__ float sSc[5];

    if (t < 5) {
        int col = k * PP + t;
        float n2 = 0.f;
#pragma unroll
        for (int c = 0; c < 8; c++) n2 += g_nrm[c * NN + col];
        sSc[t] = __expf(lws[col]) * rsqrtf(n2) * 1.4426950408889634f;
    }

    float s_[2][5];
#pragma unroll
    for (int r = 0; r < 2; r++) {
        int i = t + r * 256;
        float s0 = 0.f, s1 = 0.f, s2 = 0.f, s3 = 0.f, s4 = 0.f;
#pragma unroll
        for (int s = 0; s < SPLIT; s++) {
            const float* p = g_part + (size_t)s * BB * NN + (size_t)i * NN + k * PP;
            s0 += p[0]; s1 += p[1]; s2 += p[2]; s3 += p[3]; s4 += p[4];
        }
        s_[r][0] = s0; s_[r][1] = s1; s_[r][2] = s2; s_[r][3] = s3; s_[r][4] = s4;
    }
    __syncthreads();

    float d[2][5], Si[2];
#pragma unroll
    for (int r = 0; r < 2; r++) {
        int i = t + r * 256;
        float a0 = s_[r][0] * sSc[0], a1 = s_[r][1] * sSc[1];
        float a2 = s_[r][2] * sSc[2], a3 = s_[r][3] * sSc[3];
        float a4 = s_[r][4] * sSc[4];
        Si[r] = ((a0 + a1) + (a2 + a3)) + a4;
        d[r][0] = a0 + a0; d[r][1] = a1 + a1; d[r][2] = a2 + a2;
        d[r][3] = a3 + a3; d[r][4] = a4 + a4;
        sD[i][0] = d[r][0]; sD[i][1] = d[r][1]; sD[i][2] = d[r][2];
        sD[i][3] = d[r][3]; sD[i][4] = d[r][4]; sD[i][5] = Si[r];
    }
    __syncthreads();

    float acc0 = 0.f, acc1 = 0.f;
#pragma unroll 8
    for (int j = 0; j < BB; j++) {
        float4 v = *(const float4*)&sD[j][0];
        float2 w = *(const float2*)&sD[j][4];
        float m0 = fminf(d[0][0], v.x);
        float m1 = fminf(d[0][1], v.y);
        float m2 = fminf(d[0][2], v.z);
        float m3 = fminf(d[0][3], v.w);
        float m4 = fminf(d[0][4], w.x);
        float arg0 = ((m0 + m1) + (m2 + m3)) + (m4 - w.y);
        float e0;
        EX2(e0, arg0);
        acc0 += e0;
        float n0 = fminf(d[1][0], v.x);
        float n1 = fminf(d[1][1], v.y);
        float n2 = fminf(d[1][2], v.z);
        float n3 = fminf(d[1][3], v.w);
        float n4 = fminf(d[1][4], w.x);
        float arg1 = ((n0 + n1) + (n2 + n3)) + (n4 - w.y);
        float e1;
        EX2(e1, arg1);
        acc1 += e1;
    }
    float sc0, sc1;
    EX2(sc0, -Si[0]);
    EX2(sc1, -Si[1]);
    float bk = bias[k] - 1.0f;
    out[(size_t)t * OUTW + DD + k] = fmaf(acc0, sc0, bk);
    out[(size_t)(t + 256) * OUTW + DD + k] = fmaf(acc1, sc1, bk);
}

// ---------------------------------------------------------------------------
extern "C" void kernel_launch(void* const* d_in, const int* in_sizes, int n_in,
                              void* d_out, int out_size) {
    const float* x     = (const float*)d_in[0];   // [512, 2048]
    const float* theta = (const float*)d_in[1];   // [2048, 128, 5]
    const float* lws   = (const float*)d_in[2];   // [128, 5]
    const float* bias  = (const float*)d_in[3];   // [128]
    float* out = (float*)d_out;                   // [512, 2176]

    cudaFuncSetAttribute(gemm_mma_kernel,
                         cudaFuncAttributeMaxDynamicSharedMemorySize, GEMM_SMEM);

    prep_kernel<<<PREP_BLOCKS, 256>>>(x, theta, out);
    gemm_mma_kernel<<<dim3(NN / TN, BB / TM, SPLIT), 256, GEMM_SMEM>>>();
    pairwise_kernel<<<KK, BB / 2>>>(lws, bias, out);
}